// round 4
// baseline (speedup 1.0000x reference)
#include <cuda_runtime.h>
#include <math.h>

// VanillaRNN: out = (scan_t h = tanh(xh_t + h @ W_hh)) @ W_hy + b_y
//   xh = x @ W_xh + b_h  (precomputed association in reference!)
// B=256, S=1024, IN=128, H=512, CLASSES=128, fp32.
//
// Chaos regime (per-step perturbation gain ~3.5x) => must reproduce the
// reference's fp32 rounding EXACTLY:
//   - every GEMM output element = single serial ascending-k FMA chain
//     (matches Eigen/XLA-CPU and cuBLAS SIMT sgemm orderings)
//   - association: pre = ((x-chain) + b_h) + (h-chain)
//   - XLA EmitFastTanh, with_fma variant: clamp +-7.99881172180175781f,
//     fmaf Horner, IEEE div, |x|<4e-4 -> x   (NOT clamp 9 / not libm tanhf!)
//   - out = (h-chain) + b_y

#define B_DIM 256
#define S_DIM 1024
#define I_DIM 128
#define H_DIM 512
#define C_DIM 128

#define TM 32
#define TN 32
#define KT 16
#define NTHREADS 128
#define NCTAS 128  // (B/TM) * (H/TN) = 8 * 16

__device__ float g_h[2][B_DIM * H_DIM];
__device__ unsigned g_bar_count = 0;
__device__ unsigned g_bar_gen = 0;

__device__ __forceinline__ void grid_barrier()
{
    __syncthreads();
    if (threadIdx.x == 0) {
        volatile unsigned* genp = &g_bar_gen;
        unsigned gen = *genp;
        __threadfence();
        if (atomicAdd(&g_bar_count, 1u) == NCTAS - 1u) {
            g_bar_count = 0;
            __threadfence();
            *genp = gen + 1u;
        } else {
            while (*genp == gen) { }
        }
        __threadfence();
    }
    __syncthreads();
}

// XLA EmitFastTanh (with_fma) == Eigen generic_fast_tanh_float, bit-faithful.
__device__ __forceinline__ float xla_tanh(float x)
{
    const float kClamp = 7.99881172180175781f;
    const float a1  =  4.89352455891786e-03f;
    const float a3  =  6.37261928875436e-04f;
    const float a5  =  1.48572235717979e-05f;
    const float a7  =  5.12229709037114e-08f;
    const float a9  = -8.60467152213735e-11f;
    const float a11 =  2.00018790482477e-13f;
    const float a13 = -2.76076847742355e-16f;
    const float b0  =  4.89352518554385e-03f;
    const float b2  =  2.26843463243900e-03f;
    const float b4  =  1.18534705686654e-04f;
    const float b6  =  1.19825839466702e-06f;

    float xc = fminf(fmaxf(x, -kClamp), kClamp);
    float x2 = __fmul_rn(xc, xc);
    float p = fmaf(x2, a13, a11);
    p = fmaf(x2, p, a9);
    p = fmaf(x2, p, a7);
    p = fmaf(x2, p, a5);
    p = fmaf(x2, p, a3);
    p = fmaf(x2, p, a1);
    p = __fmul_rn(xc, p);
    float q = fmaf(x2, b6, b4);
    q = fmaf(x2, q, b2);
    q = fmaf(x2, q, b0);
    float r = __fdiv_rn(p, q);
    return (fabsf(x) < 0.0004f) ? x : r;
}

__global__ void __launch_bounds__(NTHREADS, 1)
rnn_recur_kernel(const float* __restrict__ x,
                 const float* __restrict__ W_hh,
                 const float* __restrict__ W_xh,
                 const float* __restrict__ b_h)
{
    __shared__ float A_s[2][KT][TM + 2];
    __shared__ float B_s[2][KT][TN];
    __shared__ float X_s[I_DIM][TM + 2];
    __shared__ float Wxh_s[I_DIM][TN];

    const int tid = threadIdx.x;
    const int tx = tid & 7;    // 8 n-groups * 4 cols = 32
    const int ty = tid >> 3;   // 16 m-groups * 2 rows = 32
    const int bm = blockIdx.x >> 4;
    const int bn = blockIdx.x & 15;
    const int b0 = bm * TM;
    const int n0 = bn * TN;

    // Cache W_xh column tile [I_DIM x TN] once (time-invariant).
    {
        const int r0 = tid >> 3;
        const int cc = (tid & 7) * 4;
        for (int r = r0; r < I_DIM; r += 16)
            *(float4*)&Wxh_s[r][cc] = *(const float4*)&W_xh[r * H_DIM + n0 + cc];
    }
    const float4 bh4 = *(const float4*)&b_h[n0 + tx * 4];

    // h0 = 0
    {
        const float4 z = make_float4(0.f, 0.f, 0.f, 0.f);
        *(float4*)&g_h[0][(b0 + ty * 2 + 0) * H_DIM + n0 + tx * 4] = z;
        *(float4*)&g_h[0][(b0 + ty * 2 + 1) * H_DIM + n0 + tx * 4] = z;
    }
    grid_barrier();

    const int lmA = tid >> 2;
    const int lkA = (tid & 3) * 4;
    const int kbB = tid >> 3;
    const int nbB = (tid & 7) * 4;

    for (int t = 0; t < S_DIM; ++t) {
        const int cur = t & 1;
        const float* __restrict__ hcur = g_h[cur];
        float* __restrict__ hnxt = g_h[cur ^ 1];

        // h @ W_hh accumulator chains (start at 0, k ascending)
        float a00 = 0.f, a01 = 0.f, a02 = 0.f, a03 = 0.f;
        float a10 = 0.f, a11 = 0.f, a12 = 0.f, a13 = 0.f;

        // Stage x[b0..b0+31, t, :] transposed into X_s
        {
            const int m  = tid >> 2;
            const int ib = (tid & 3) * 4;
            const float* xp = x + ((size_t)(b0 + m) * S_DIM + (size_t)t) * I_DIM;
            #pragma unroll
            for (int it = 0; it < 8; ++it) {
                const int i = ib + it * 16;
                const float4 v = *(const float4*)&xp[i];
                X_s[i + 0][m] = v.x;
                X_s[i + 1][m] = v.y;
                X_s[i + 2][m] = v.z;
                X_s[i + 3][m] = v.w;
            }
        }

        // ---- mainloop: accH = serial ascending-k chain of h @ W_hh ----
        float4 aR = *(const float4*)&hcur[(b0 + lmA) * H_DIM + lkA];
        float4 bR = *(const float4*)&W_hh[kbB * H_DIM + n0 + nbB];
        A_s[0][lkA + 0][lmA] = aR.x;
        A_s[0][lkA + 1][lmA] = aR.y;
        A_s[0][lkA + 2][lmA] = aR.z;
        A_s[0][lkA + 3][lmA] = aR.w;
        *(float4*)&B_s[0][kbB][nbB] = bR;
        __syncthreads();

        #pragma unroll 1
        for (int c = 0; c < H_DIM / KT; ++c) {
            const int buf = c & 1;
            const int k0n = (c + 1) * KT;
            const bool more = (c + 1 < H_DIM / KT);
            if (more) {
                aR = *(const float4*)&hcur[(b0 + lmA) * H_DIM + k0n + lkA];
                bR = *(const float4*)&W_hh[(k0n + kbB) * H_DIM + n0 + nbB];
            }
            #pragma unroll
            for (int kk = 0; kk < KT; ++kk) {
                const float2 a = *(const float2*)&A_s[buf][kk][ty * 2];
                const float4 b = *(const float4*)&B_s[buf][kk][tx * 4];
                a00 = fmaf(a.x, b.x, a00); a01 = fmaf(a.x, b.y, a01);
                a02 = fmaf(a.x, b.z, a02); a03 = fmaf(a.x, b.w, a03);
                a10 = fmaf(a.y, b.x, a10); a11 = fmaf(a.y, b.y, a11);
                a12 = fmaf(a.y, b.z, a12); a13 = fmaf(a.y, b.w, a13);
            }
            if (more) {
                const int nb2 = buf ^ 1;
                A_s[nb2][lkA + 0][lmA] = aR.x;
                A_s[nb2][lkA + 1][lmA] = aR.y;
                A_s[nb2][lkA + 2][lmA] = aR.z;
                A_s[nb2][lkA + 3][lmA] = aR.w;
                *(float4*)&B_s[nb2][kbB][nbB] = bR;
            }
            __syncthreads();
        }

        // ---- separate chain: accX = x_t @ W_xh (k ascending, starts at 0) ----
        float x00 = 0.f, x01 = 0.f, x02 = 0.f, x03 = 0.f;
        float x10 = 0.f, x11 = 0.f, x12 = 0.f, x13 = 0.f;
        #pragma unroll 8
        for (int kk = 0; kk < I_DIM; ++kk) {
            const float2 a = *(const float2*)&X_s[kk][ty * 2];
            const float4 b = *(const float4*)&Wxh_s[kk][tx * 4];
            x00 = fmaf(a.x, b.x, x00); x01 = fmaf(a.x, b.y, x01);
            x02 = fmaf(a.x, b.z, x02); x03 = fmaf(a.x, b.w, x03);
            x10 = fmaf(a.y, b.x, x10); x11 = fmaf(a.y, b.y, x11);
            x12 = fmaf(a.y, b.z, x12); x13 = fmaf(a.y, b.w, x13);
        }

        // ---- epilogue: pre = ((accX + b_h) + accH); h' = xla_tanh(pre) ----
        {
            float4 o0, o1;
            o0.x = xla_tanh(__fadd_rn(__fadd_rn(x00, bh4.x), a00));
            o0.y = xla_tanh(__fadd_rn(__fadd_rn(x01, bh4.y), a01));
            o0.z = xla_tanh(__fadd_rn(__fadd_rn(x02, bh4.z), a02));
            o0.w = xla_tanh(__fadd_rn(__fadd_rn(x03, bh4.w), a03));
            o1.x = xla_tanh(__fadd_rn(__fadd_rn(x10, bh4.x), a10));
            o1.y = xla_tanh(__fadd_rn(__fadd_rn(x11, bh4.y), a11));
            o1.z = xla_tanh(__fadd_rn(__fadd_rn(x12, bh4.z), a12));
            o1.w = xla_tanh(__fadd_rn(__fadd_rn(x13, bh4.w), a13));
            *(float4*)&hnxt[(b0 + ty * 2 + 0) * H_DIM + n0 + tx * 4] = o0;
            *(float4*)&hnxt[(b0 + ty * 2 + 1) * H_DIM + n0 + tx * 4] = o1;
        }

        grid_barrier();
    }
}

__global__ void __launch_bounds__(C_DIM)
rnn_out_kernel(const float* __restrict__ W_hy,
               const float* __restrict__ b_y,
               float* __restrict__ out)
{
    __shared__ float hrow[H_DIM];
    const int b = blockIdx.x;
    const int c = threadIdx.x;
    for (int k = c; k < H_DIM; k += C_DIM)
        hrow[k] = g_h[0][b * H_DIM + k];
    __syncthreads();
    float acc = 0.f;  // serial ascending-k chain, bias added AFTER (XLA order)
    #pragma unroll 8
    for (int k = 0; k < H_DIM; ++k)
        acc = fmaf(hrow[k], W_hy[k * C_DIM + c], acc);
    out[b * C_DIM + c] = __fadd_rn(acc, b_y[c]);
}

extern "C" void kernel_launch(void* const* d_in, const int* in_sizes, int n_in,
                              void* d_out, int out_size)
{
    (void)in_sizes; (void)n_in; (void)out_size;
    const float* x    = (const float*)d_in[0];
    const float* W_hh = (const float*)d_in[1];
    const float* W_xh = (const float*)d_in[2];
    const float* W_hy = (const float*)d_in[3];
    const float* b_h  = (const float*)d_in[4];
    const float* b_y  = (const float*)d_in[5];
    float* out = (float*)d_out;

    rnn_recur_kernel<<<NCTAS, NTHREADS>>>(x, W_hh, W_xh, b_h);
    rnn_out_kernel<<<B_DIM, C_DIM>>>(W_hy, b_y, out);
}

// round 5
// speedup vs baseline: 1.0563x; 1.0563x over previous
#include <cuda_runtime.h>
#include <math.h>

// VanillaRNN bit-exact vs XLA reference:
//   xh = x @ W_xh + b_h      (serial ascending-k fmaf chain, + b_h after)
//   h' = fast_tanh((xh + (h @ W_hh chain)))   for 1024 steps
//   out = (h @ W_hy chain) + b_y
// B=256, S=1024, IN=128, H=512, CLASSES=128, fp32.
//
// Perf design (round 5):
//   - persistent kernel, 128 CTAs x 128 thr, each CTA owns a 32x32 tile of h
//   - W_hh column tile resident in smem (64 KB, loaded once)
//   - h tile staged to smem once per step via __ldcg (L2-coherent), 1 sync/step
//   - mainloop: 512 kk of pure smem reads + FFMA (no global, no sync)
//   - per-bm-group barrier (16 CTAs each, 8 independent lines)

#define B_DIM 256
#define S_DIM 1024
#define I_DIM 128
#define H_DIM 512
#define C_DIM 128

#define TM 32
#define TN 32
#define NTHREADS 128
#define NCTAS 128          // 8 bm-groups x 16 bn
#define GROUP_SZ 16

#define AP (TM + 2)        // A_s row pad: 34 floats

// smem layout (floats): W_s[512*32] | A_s[512*34] | Wxh_s[128*32] | X_s[128*34]
#define W_OFF   0
#define A_OFF   (H_DIM * TN)
#define WXH_OFF (A_OFF + H_DIM * AP)
#define X_OFF   (WXH_OFF + I_DIM * TN)
#define SMEM_FLOATS (X_OFF + I_DIM * AP)

__device__ float g_h[2][B_DIM * H_DIM];
__device__ unsigned g_cnt[8 * 32];   // one line per bm-group
__device__ unsigned g_gen[8 * 32];

__device__ __forceinline__ void group_barrier(int bm)
{
    __threadfence();      // order this thread's h STGs before the flag
    __syncthreads();
    if (threadIdx.x == 0) {
        volatile unsigned* genp = &g_gen[bm * 32];
        const unsigned gen = *genp;
        if (atomicAdd(&g_cnt[bm * 32], 1u) == GROUP_SZ - 1u) {
            *(volatile unsigned*)&g_cnt[bm * 32] = 0u;
            __threadfence();
            *genp = gen + 1u;
        } else {
            while (*genp == gen) { }
        }
        __threadfence();
    }
    __syncthreads();
}

// XLA EmitFastTanh (with_fma) == Eigen generic_fast_tanh_float, bit-faithful.
__device__ __forceinline__ float xla_tanh(float x)
{
    const float kClamp = 7.99881172180175781f;
    const float a1  =  4.89352455891786e-03f;
    const float a3  =  6.37261928875436e-04f;
    const float a5  =  1.48572235717979e-05f;
    const float a7  =  5.12229709037114e-08f;
    const float a9  = -8.60467152213735e-11f;
    const float a11 =  2.00018790482477e-13f;
    const float a13 = -2.76076847742355e-16f;
    const float b0  =  4.89352518554385e-03f;
    const float b2  =  2.26843463243900e-03f;
    const float b4  =  1.18534705686654e-04f;
    const float b6  =  1.19825839466702e-06f;

    float xc = fminf(fmaxf(x, -kClamp), kClamp);
    float x2 = __fmul_rn(xc, xc);
    float p = fmaf(x2, a13, a11);
    p = fmaf(x2, p, a9);
    p = fmaf(x2, p, a7);
    p = fmaf(x2, p, a5);
    p = fmaf(x2, p, a3);
    p = fmaf(x2, p, a1);
    p = __fmul_rn(xc, p);
    float q = fmaf(x2, b6, b4);
    q = fmaf(x2, q, b2);
    q = fmaf(x2, q, b0);
    float r = __fdiv_rn(p, q);
    return (fabsf(x) < 0.0004f) ? x : r;
}

__global__ void __launch_bounds__(NTHREADS, 1)
rnn_recur_kernel(const float* __restrict__ x,
                 const float* __restrict__ W_hh,
                 const float* __restrict__ W_xh,
                 const float* __restrict__ b_h)
{
    extern __shared__ float smem[];
    float* __restrict__ W_s   = smem + W_OFF;    // [k][32]
    float* __restrict__ A_s   = smem + A_OFF;    // [k][34]
    float* __restrict__ Wxh_s = smem + WXH_OFF;  // [i][32]
    float* __restrict__ X_s   = smem + X_OFF;    // [i][34]

    const int tid = threadIdx.x;
    const int tx = tid & 7;    // 8 n-groups * 4 cols = 32
    const int ty = tid >> 3;   // 16 m-groups * 2 rows = 32
    const int bm = blockIdx.x >> 4;
    const int bn = blockIdx.x & 15;
    const int b0 = bm * TM;
    const int n0 = bn * TN;

    // ---- one-time: W_hh column tile -> W_s, W_xh column tile -> Wxh_s ----
    for (int idx = tid; idx < H_DIM * 8; idx += NTHREADS) {   // 4096 float4
        const int r = idx >> 3, q = idx & 7;
        *(float4*)&W_s[r * TN + q * 4] =
            __ldg((const float4*)&W_hh[r * H_DIM + n0 + q * 4]);
    }
    for (int idx = tid; idx < I_DIM * 8; idx += NTHREADS) {   // 1024 float4
        const int r = idx >> 3, q = idx & 7;
        *(float4*)&Wxh_s[r * TN + q * 4] =
            __ldg((const float4*)&W_xh[r * H_DIM + n0 + q * 4]);
    }
    const float4 bh4 = *(const float4*)&b_h[n0 + tx * 4];

    const int lmA = tid >> 2;          // m row this thread stages (0..31)
    const int lkA = (tid & 3) * 4;     // k sub-offset (0,4,8,12)
    const int rowbase = (b0 + lmA) * H_DIM;

    #pragma unroll 1
    for (int t = 0; t < S_DIM; ++t) {
        const float* __restrict__ hcur = g_h[t & 1];
        float* __restrict__ hnxt = g_h[(t & 1) ^ 1];

        // ---- stage x[b0..b0+31, t, :] transposed into X_s ----
        {
            const int m  = tid >> 2;
            const int ib = (tid & 3) * 4;
            const float* xp = x + ((size_t)(b0 + m) * S_DIM + (size_t)t) * I_DIM;
            #pragma unroll
            for (int it = 0; it < 8; ++it) {
                const int i = ib + it * 16;
                const float4 v = __ldg((const float4*)&xp[i]);
                X_s[(i + 0) * AP + m] = v.x;
                X_s[(i + 1) * AP + m] = v.y;
                X_s[(i + 2) * AP + m] = v.z;
                X_s[(i + 3) * AP + m] = v.w;
            }
        }

        // ---- stage h tile [32 x 512] into A_s (L2-coherent loads, high MLP) ----
        if (t > 0) {
            #pragma unroll
            for (int half = 0; half < 2; ++half) {
                float4 v[16];
                #pragma unroll
                for (int j = 0; j < 16; ++j)
                    v[j] = __ldcg((const float4*)&hcur[rowbase + (half * 16 + j) * 16 + lkA]);
                #pragma unroll
                for (int j = 0; j < 16; ++j) {
                    const int k = (half * 16 + j) * 16 + lkA;
                    A_s[(k + 0) * AP + lmA] = v[j].x;
                    A_s[(k + 1) * AP + lmA] = v[j].y;
                    A_s[(k + 2) * AP + lmA] = v[j].z;
                    A_s[(k + 3) * AP + lmA] = v[j].w;
                }
            }
        }
        __syncthreads();

        // ---- accH: serial ascending-k fmaf chain of h @ W_hh ----
        float a00 = 0.f, a01 = 0.f, a02 = 0.f, a03 = 0.f;
        float a10 = 0.f, a11 = 0.f, a12 = 0.f, a13 = 0.f;
        if (t > 0) {
            #pragma unroll 8
            for (int kk = 0; kk < H_DIM; ++kk) {
                const float2 a = *(const float2*)&A_s[kk * AP + ty * 2];
                const float4 w = *(const float4*)&W_s[kk * TN + tx * 4];
                a00 = fmaf(a.x, w.x, a00); a01 = fmaf(a.x, w.y, a01);
                a02 = fmaf(a.x, w.z, a02); a03 = fmaf(a.x, w.w, a03);
                a10 = fmaf(a.y, w.x, a10); a11 = fmaf(a.y, w.y, a11);
                a12 = fmaf(a.y, w.z, a12); a13 = fmaf(a.y, w.w, a13);
            }
        }

        // ---- accX: serial ascending-k fmaf chain of x_t @ W_xh ----
        float x00 = 0.f, x01 = 0.f, x02 = 0.f, x03 = 0.f;
        float x10 = 0.f, x11 = 0.f, x12 = 0.f, x13 = 0.f;
        #pragma unroll 8
        for (int kk = 0; kk < I_DIM; ++kk) {
            const float2 a = *(const float2*)&X_s[kk * AP + ty * 2];
            const float4 w = *(const float4*)&Wxh_s[kk * TN + tx * 4];
            x00 = fmaf(a.x, w.x, x00); x01 = fmaf(a.x, w.y, x01);
            x02 = fmaf(a.x, w.z, x02); x03 = fmaf(a.x, w.w, x03);
            x10 = fmaf(a.y, w.x, x10); x11 = fmaf(a.y, w.y, x11);
            x12 = fmaf(a.y, w.z, x12); x13 = fmaf(a.y, w.w, x13);
        }

        // ---- epilogue: h' = tanh(((accX + b_h) + accH)) ----
        {
            float4 o0, o1;
            o0.x = xla_tanh(__fadd_rn(__fadd_rn(x00, bh4.x), a00));
            o0.y = xla_tanh(__fadd_rn(__fadd_rn(x01, bh4.y), a01));
            o0.z = xla_tanh(__fadd_rn(__fadd_rn(x02, bh4.z), a02));
            o0.w = xla_tanh(__fadd_rn(__fadd_rn(x03, bh4.w), a03));
            o1.x = xla_tanh(__fadd_rn(__fadd_rn(x10, bh4.x), a10));
            o1.y = xla_tanh(__fadd_rn(__fadd_rn(x11, bh4.y), a11));
            o1.z = xla_tanh(__fadd_rn(__fadd_rn(x12, bh4.z), a12));
            o1.w = xla_tanh(__fadd_rn(__fadd_rn(x13, bh4.w), a13));
            *(float4*)&hnxt[(b0 + ty * 2 + 0) * H_DIM + n0 + tx * 4] = o0;
            *(float4*)&hnxt[(b0 + ty * 2 + 1) * H_DIM + n0 + tx * 4] = o1;
        }

        // needed across the WHOLE group: tile readers span all bn of this bm,
        // and the next step's write buffer must be fully consumed group-wide.
        group_barrier(bm);
    }
    // final h in g_h[0] (S_DIM even)
}

__global__ void __launch_bounds__(C_DIM)
rnn_out_kernel(const float* __restrict__ W_hy,
               const float* __restrict__ b_y,
               float* __restrict__ out)
{
    __shared__ float hrow[H_DIM];
    const int b = blockIdx.x;
    const int c = threadIdx.x;
    for (int k = c; k < H_DIM; k += C_DIM)
        hrow[k] = g_h[0][b * H_DIM + k];
    __syncthreads();
    float acc = 0.f;  // serial ascending-k chain, bias added AFTER (XLA order)
    #pragma unroll 8
    for (int k = 0; k < H_DIM; ++k)
        acc = fmaf(hrow[k], W_hy[k * C_DIM + c], acc);
    out[b * C_DIM + c] = __fadd_rn(acc, b_y[c]);
}

extern "C" void kernel_launch(void* const* d_in, const int* in_sizes, int n_in,
                              void* d_out, int out_size)
{
    (void)in_sizes; (void)n_in; (void)out_size;
    const float* x    = (const float*)d_in[0];
    const float* W_hh = (const float*)d_in[1];
    const float* W_xh = (const float*)d_in[2];
    const float* W_hy = (const float*)d_in[3];
    const float* b_h  = (const float*)d_in[4];
    const float* b_y  = (const float*)d_in[5];
    float* out = (float*)d_out;

    const int smem_bytes = SMEM_FLOATS * (int)sizeof(float);   // ~165 KB
    cudaFuncSetAttribute(rnn_recur_kernel,
                         cudaFuncAttributeMaxDynamicSharedMemorySize, smem_bytes);

    rnn_recur_kernel<<<NCTAS, NTHREADS, smem_bytes>>>(x, W_hh, W_xh, b_h);
    rnn_out_kernel<<<B_DIM, C_DIM>>>(W_hy, b_y, out);
}